// round 12
// baseline (speedup 1.0000x reference)
#include <cuda_runtime.h>
#include <cuda_bf16.h>
#include <cuda_fp16.h>
#include <cstdint>

#define B_   8
#define C_   128
#define N_   4096
#define M_   1024
#define DQK  16
#define DV   64

// ---------------- device scratch ----------------
static __device__ __nv_bfloat16 g_theta_bf[B_ * N_ * DQK];   // [b][n][16] (pre-scaled by log2e)
static __device__ __nv_bfloat16 g_phi_bf  [B_ * M_ * DQK];   // [b][m][16]
static __device__ __half        g_gT      [B_ * DV * M_];    // [b][ch][m]  (f16)

// ---------------- helpers ----------------
__device__ __forceinline__ uint32_t smem_u32(const void* p) {
    uint32_t a;
    asm("{ .reg .u64 t; cvta.to.shared.u64 t, %1; cvt.u32.u64 %0, t; }" : "=r"(a) : "l"(p));
    return a;
}
__device__ __forceinline__ void cp16(uint32_t dst, const void* src) {
    asm volatile("cp.async.cg.shared.global [%0], [%1], 16;" :: "r"(dst), "l"(src));
}
#define CP_COMMIT() asm volatile("cp.async.commit_group;" ::: "memory")
#define CP_WAIT(n)  asm volatile("cp.async.wait_group %0;" :: "n"(n) : "memory")

__device__ __forceinline__ void mma_bf16(float d[4], const uint32_t a[4], const uint32_t b[2]) {
    asm volatile("mma.sync.aligned.m16n8k16.row.col.f32.bf16.bf16.f32 "
        "{%0,%1,%2,%3}, {%4,%5,%6,%7}, {%8,%9}, {%0,%1,%2,%3};"
        : "+f"(d[0]), "+f"(d[1]), "+f"(d[2]), "+f"(d[3])
        : "r"(a[0]), "r"(a[1]), "r"(a[2]), "r"(a[3]), "r"(b[0]), "r"(b[1]));
}
__device__ __forceinline__ void mma_f16_f32(float d[4], const uint32_t a[4], const uint32_t b[2]) {
    asm volatile("mma.sync.aligned.m16n8k16.row.col.f32.f16.f16.f32 "
        "{%0,%1,%2,%3}, {%4,%5,%6,%7}, {%8,%9}, {%0,%1,%2,%3};"
        : "+f"(d[0]), "+f"(d[1]), "+f"(d[2]), "+f"(d[3])
        : "r"(a[0]), "r"(a[1]), "r"(a[2]), "r"(a[3]), "r"(b[0]), "r"(b[1]));
}
// f16 accumulator PV MMA (d = 2 regs of f16x2)
__device__ __forceinline__ void mma_f16_f16(uint32_t d[2], const uint32_t a[4], const uint32_t b[2]) {
    asm volatile("mma.sync.aligned.m16n8k16.row.col.f16.f16.f16.f16 "
        "{%0,%1}, {%2,%3,%4,%5}, {%6,%7}, {%0,%1};"
        : "+r"(d[0]), "+r"(d[1])
        : "r"(a[0]), "r"(a[1]), "r"(a[2]), "r"(a[3]), "r"(b[0]), "r"(b[1]));
}
__device__ __forceinline__ uint32_t packbf(float lo, float hi) {
    uint32_t r;
    asm("cvt.rn.satfinite.bf16x2.f32 %0, %1, %2;" : "=r"(r) : "f"(hi), "f"(lo));
    return r;
}
__device__ __forceinline__ uint32_t packh2(float lo, float hi) {
    uint32_t r;
    asm("cvt.rn.f16x2.f32 %0, %1, %2;" : "=r"(r) : "f"(hi), "f"(lo));
    return r;
}
__device__ __forceinline__ uint32_t exh2(uint32_t v) {
    uint32_t r;
    asm("ex2.approx.f16x2 %0, %1;" : "=r"(r) : "r"(v));
    return r;
}
__device__ __forceinline__ void ldsm_x4(uint32_t r[4], uint32_t addr) {
    asm volatile("ldmatrix.sync.aligned.m8n8.x4.shared.b16 {%0,%1,%2,%3}, [%4];"
        : "=r"(r[0]), "=r"(r[1]), "=r"(r[2]), "=r"(r[3]) : "r"(addr));
}
__device__ __forceinline__ void ldsm_x2t(uint32_t r[2], uint32_t addr) {
    asm volatile("ldmatrix.sync.aligned.m8n8.x2.trans.shared.b16 {%0,%1}, [%2];"
        : "=r"(r[0]), "=r"(r[1]) : "r"(addr));
}

// ============================================================================
// Kernel 1: all projections as one bf16 tensor-core GEMM + fused 2x2 pooling.
// theta pre-scaled by log2(e); g stored as f16.  (unchanged)
// ============================================================================
#define PROJ_WS   34816
#define SMEM_PROJ 60928

__global__ void __launch_bounds__(256) k_proj(const float* __restrict__ x,
                       const float* __restrict__ Wth,
                       const float* __restrict__ Wph, const float* __restrict__ Wg) {
    extern __shared__ __align__(16) unsigned char smem[];
    __nv_bfloat16* xs = (__nv_bfloat16*)smem;               // [128][136]
    __nv_bfloat16* ws = (__nv_bfloat16*)(smem + PROJ_WS);   // [96][136]
    int tid = threadIdx.x, b = blockIdx.y, bx = blockIdx.x;
    int n0 = bx * 128;

#pragma unroll
    for (int k = 0; k < 12; k++) {
        int e = k * 256 + tid;
        int row = e >> 5, c4 = e & 31;
        const float* src = (row < 16) ? &Wth[row * 128]
                         : (row < 32) ? &Wph[(row - 16) * 128]
                                      : &Wg[(row - 32) * 128];
        float sc = (row < 16) ? 1.4426950408889634f : 1.0f;
        float4 v = *(const float4*)&src[c4 * 4];
        uint32_t* d = (uint32_t*)&ws[row * 136 + c4 * 4];
        d[0] = packbf(v.x * sc, v.y * sc); d[1] = packbf(v.z * sc, v.w * sc);
    }
    const float* xp = x + ((size_t)b * C_) * N_ + n0;
#pragma unroll
    for (int k = 0; k < 16; k++) {
        int e = k * 256 + tid;
        int ch = e >> 5, p4 = e & 31;
        float4 v = *(const float4*)&xp[(size_t)ch * N_ + p4 * 4];
        uint32_t* d = (uint32_t*)&xs[ch * 136 + p4 * 4];
        d[0] = packbf(v.x, v.y); d[1] = packbf(v.z, v.w);
    }
    __syncthreads();

    int warp = tid >> 5, lane = tid & 31, g = lane >> 2, t = lane & 3;
    int px0 = warp * 16;
    int aq = lane >> 3;
    int ar = (aq & 1) * 8 + (lane & 7), ac = (aq >> 1) * 8;
    int bl = lane & 15;

    float acc[6][2][4];
#pragma unroll
    for (int mi = 0; mi < 6; mi++)
#pragma unroll
        for (int ni = 0; ni < 2; ni++)
#pragma unroll
            for (int i = 0; i < 4; i++) acc[mi][ni][i] = 0.f;

#pragma unroll
    for (int k0 = 0; k0 < 128; k0 += 16) {
        uint32_t bf[2][2];
#pragma unroll
        for (int ni = 0; ni < 2; ni++)
            ldsm_x2t(bf[ni], smem_u32(&xs[(k0 + bl) * 136 + px0 + ni * 8]));
#pragma unroll
        for (int mi = 0; mi < 6; mi++) {
            uint32_t af[4];
            ldsm_x4(af, smem_u32(&ws[(mi * 16 + ar) * 136 + k0 + ac]));
            mma_bf16(acc[mi][0], af, bf[0]);
            mma_bf16(acc[mi][1], af, bf[1]);
        }
    }

#pragma unroll
    for (int ni = 0; ni < 2; ni++) {
        int px = px0 + ni * 8 + 2 * t;
        __nv_bfloat16* base = &g_theta_bf[((size_t)b * N_ + n0 + px) * DQK];
        base[g]          = __float2bfloat16(acc[0][ni][0]);
        base[16 + g]     = __float2bfloat16(acc[0][ni][1]);
        base[g + 8]      = __float2bfloat16(acc[0][ni][2]);
        base[16 + g + 8] = __float2bfloat16(acc[0][ni][3]);
    }

    __syncthreads();
    __nv_bfloat16* st = xs;   // rows 0..15 phi (bf16), rows 16..79 g (f16 bits)
#pragma unroll
    for (int mi = 1; mi < 6; mi++)
#pragma unroll
        for (int ni = 0; ni < 2; ni++) {
            int ro = mi * 16 - 16, pxx = px0 + ni * 8 + 2 * t;
            uint32_t p0, p1;
            if (mi == 1) {
                p0 = packbf(acc[mi][ni][0], acc[mi][ni][1]);
                p1 = packbf(acc[mi][ni][2], acc[mi][ni][3]);
            } else {
                p0 = packh2(acc[mi][ni][0], acc[mi][ni][1]);
                p1 = packh2(acc[mi][ni][2], acc[mi][ni][3]);
            }
            *(uint32_t*)&st[(ro + g) * 136 + pxx]     = p0;
            *(uint32_t*)&st[(ro + g + 8) * 136 + pxx] = p1;
        }
    __syncthreads();

    int cell0 = bx * 32;
#pragma unroll
    for (int k = 0; k < 10; k++) {
        int e = k * 256 + tid;
        int o = e >> 5, q = e & 31;
        if (o < 16) {
            __nv_bfloat162 v0 = *(__nv_bfloat162*)&st[o * 136 + 2 * q];
            __nv_bfloat162 v1 = *(__nv_bfloat162*)&st[o * 136 + 64 + 2 * q];
            float m = fmaxf(fmaxf(__low2float(v0), __high2float(v0)),
                            fmaxf(__low2float(v1), __high2float(v1)));
            g_phi_bf[((size_t)b * M_ + cell0 + q) * DQK + o] = __float2bfloat16(m);
        } else {
            __half2 v0 = *(__half2*)&st[o * 136 + 2 * q];
            __half2 v1 = *(__half2*)&st[o * 136 + 64 + 2 * q];
            float m = fmaxf(fmaxf(__low2float(v0), __high2float(v0)),
                            fmaxf(__low2float(v1), __high2float(v1)));
            g_gT[((size_t)b * DV + (o - 16)) * M_ + cell0 + q] = __float2half(m);
        }
    }
}

// ============================================================================
// Kernel 2: fused attention + W_o + residual.
// Warp = (q-tile of 32, key-half of 512). Each warp: 4 chunks x 8 kt.
// PV accumulates in f16 with P scaled by 2^-6 (score accum init = -6 in log2
// units; z from the SAME scaled P via ones-MMA, so o/z is invariant).
// smem map (mainloop):
//   [0,6144)        theta [128q][24bf16] (48B rows)
//   [6144,30720)    phi 4 bufs (kh*2+pb) x 6144 (48B rows)
//   [30720,100352)  gT  4 bufs x 17408 ([64ch][136 f16], 272B rows)
// epilogue overlay:
//   obuf fp32 [128q][68] @0 (34816) | zbuf fp32 [2][128] @34816
//   st fp32 [128oc][132q] @0 (67584, phase 3+)
//   Wo bf16 [128oc][72] @67584 (144B rows) | obn bf16 [64ic][136q] @86016
// ============================================================================
#define TH_OFF   0
#define PHI_OFF  6144
#define PHI_BUF  6144
#define GT_OFF   30720
#define GT_BUF   17408
#define ZB_OFF   34816
#define WO_OFF2  67584
#define OBN_OFF  86016
#define SMEM_ATTN 103424

__global__ void __launch_bounds__(256, 2) k_attn(const float* __restrict__ x,
                      const float* __restrict__ Wo,
                      const float* __restrict__ gammap, float* __restrict__ out) {
    extern __shared__ __align__(16) unsigned char smem[];
    int tid = threadIdx.x, b = blockIdx.y, q0 = blockIdx.x * 128;
    int warp = tid >> 5, lane = tid & 31, g = lane >> 2, t = lane & 3;
    int qt = warp & 3, kh = warp >> 2;
    uint32_t sb = smem_u32(smem);
    const uint32_t ONES2 = 0x3C003C00u;
    const float SBIAS = -6.0f;          // P scaled by 2^-6 against f16 overflow

    // ldmatrix lane maps
    int lo   = ((lane >> 4) & 1) * 8 + (lane & 7);
    int hi8  = ((lane >> 3) & 1) * 8;
    int arow = ((lane >> 3) & 1) * 8 + (lane & 7);
    int acol = ((lane >> 4) & 1) * 8;
    int bl   = lane & 15;

    // theta: 128 rows x 32B -> 48B-stride rows
    cp16(sb + TH_OFF + (tid >> 1) * 48 + (tid & 1) * 16,
         (const char*)&g_theta_bf[((size_t)b * N_ + q0) * DQK] + tid * 16);

    // load absolute chunk c into buffer slot (half, pb)
    auto issue_chunk = [&](int c, int half, int pb) {
        const char* gsrc = (const char*)&g_gT[((size_t)b * DV) * M_ + c * 128];
        uint32_t gdst = sb + GT_OFF + (half * 2 + pb) * GT_BUF;
#pragma unroll
        for (int r = 0; r < 4; r++) {
            int i = r * 256 + tid;
            int ch = i >> 4, off = i & 15;
            cp16(gdst + ch * 272 + off * 16, gsrc + (size_t)ch * 2048 + off * 16);
        }
        cp16(sb + PHI_OFF + (half * 2 + pb) * PHI_BUF + (tid >> 1) * 48 + (tid & 1) * 16,
             (const char*)&g_phi_bf[((size_t)b * M_ + c * 128) * DQK] + tid * 16);
    };
    issue_chunk(0, 0, 0);
    issue_chunk(4, 1, 0);
    CP_COMMIT();

    uint32_t thA[2][4];
    uint32_t o16[2][8][2];
    float zacc[2][4];
#pragma unroll
    for (int m = 0; m < 2; m++) {
#pragma unroll
        for (int n = 0; n < 8; n++) { o16[m][n][0] = 0u; o16[m][n][1] = 0u; }
#pragma unroll
        for (int i = 0; i < 4; i++) zacc[m][i] = 0.f;
    }

    for (int s = 0; s < 4; s++) {
        int pb = s & 1;
        if (s < 3) {
            issue_chunk(s + 1, 0, pb ^ 1);
            issue_chunk(s + 5, 1, pb ^ 1);
            CP_COMMIT(); CP_WAIT(1);
        } else {
            CP_WAIT(0);
        }
        __syncthreads();

        if (s == 0) {
            const __nv_bfloat16* ths = (const __nv_bfloat16*)(smem + TH_OFF);
#pragma unroll
            for (int m = 0; m < 2; m++)
                ldsm_x4(thA[m], smem_u32(&ths[(qt * 32 + m * 16 + arow) * 24 + acol]));
        }
        const __nv_bfloat16* phis =
            (const __nv_bfloat16*)(smem + PHI_OFF + (kh * 2 + pb) * PHI_BUF);
        const __half* gts = (const __half*)(smem + GT_OFF + (kh * 2 + pb) * GT_BUF);

#pragma unroll
        for (int kt = 0; kt < 8; kt++) {
            uint32_t pbq[4];
            ldsm_x4(pbq, smem_u32(&phis[(kt * 16 + lo) * 24 + hi8]));
            uint32_t gbq[4][4];
#pragma unroll
            for (int np = 0; np < 4; np++)
                ldsm_x4(gbq[np], smem_u32(&gts[(np * 16 + lo) * 136 + kt * 16 + hi8]));

#pragma unroll
            for (int m = 0; m < 2; m++) {
                float s0[4] = {SBIAS, SBIAS, SBIAS, SBIAS};
                float s1[4] = {SBIAS, SBIAS, SBIAS, SBIAS};
                mma_bf16(s0, thA[m], &pbq[0]);
                mma_bf16(s1, thA[m], &pbq[2]);

                uint32_t pa[4];
                pa[0] = exh2(packh2(s0[0], s0[1]));
                pa[1] = exh2(packh2(s0[2], s0[3]));
                pa[2] = exh2(packh2(s1[0], s1[1]));
                pa[3] = exh2(packh2(s1[2], s1[3]));

                uint32_t bones[2] = {ONES2, ONES2};
                mma_f16_f32(zacc[m], pa, bones);
#pragma unroll
                for (int np = 0; np < 4; np++) {
                    mma_f16_f16(o16[m][2*np],   pa, &gbq[np][0]);
                    mma_f16_f16(o16[m][2*np+1], pa, &gbq[np][2]);
                }
            }
        }
        __syncthreads();
    }

    // ---------------- epilogue ----------------
    float* obuf = (float*)smem;                       // [128q][68]
    float* zbuf = (float*)(smem + ZB_OFF);            // [2][128]

    // P1: kh0 writes partials; kh1 adds.
    if (kh == 0) {
#pragma unroll
        for (int m = 0; m < 2; m++) {
            int q = qt * 32 + m * 16 + g;
#pragma unroll
            for (int nb = 0; nb < 8; nb++) {
                int ch = nb * 8 + 2 * t;
                float2 v0 = __half22float2(*(__half2*)&o16[m][nb][0]);
                float2 v1 = __half22float2(*(__half2*)&o16[m][nb][1]);
                *(float2*)&obuf[q * 68 + ch]       = v0;
                *(float2*)&obuf[(q + 8) * 68 + ch] = v1;
            }
            if (t == 0) {
                zbuf[q]     = zacc[m][0];
                zbuf[q + 8] = zacc[m][2];
            }
        }
    }
    __syncthreads();
    if (kh == 1) {
#pragma unroll
        for (int m = 0; m < 2; m++) {
            int q = qt * 32 + m * 16 + g;
#pragma unroll
            for (int nb = 0; nb < 8; nb++) {
                int ch = nb * 8 + 2 * t;
                float2 v0 = __half22float2(*(__half2*)&o16[m][nb][0]);
                float2 v1 = __half22float2(*(__half2*)&o16[m][nb][1]);
                float2 a0 = *(float2*)&obuf[q * 68 + ch];
                float2 a1 = *(float2*)&obuf[(q + 8) * 68 + ch];
                a0.x += v0.x; a0.y += v0.y;
                a1.x += v1.x; a1.y += v1.y;
                *(float2*)&obuf[q * 68 + ch]       = a0;
                *(float2*)&obuf[(q + 8) * 68 + ch] = a1;
            }
            if (t == 0) {
                zbuf[128 + q]     = zacc[m][0];
                zbuf[128 + q + 8] = zacc[m][2];
            }
        }
    }
    __syncthreads();

    // P2: normalize + pack to obn [64ic][136q] bf16; load Wo -> smem [128][72]
    {
        __nv_bfloat16* obn = (__nv_bfloat16*)(smem + OBN_OFF);
        int q = tid & 127, hi = tid >> 7;
        float inv = 1.f / (zbuf[q] + zbuf[128 + q]);
#pragma unroll
        for (int k = 0; k < 32; k++) {
            int ic = 2 * k + hi;
            obn[ic * 136 + q] = __float2bfloat16(obuf[q * 68 + ic] * inv);
        }
        uint32_t* wo32 = (uint32_t*)(smem + WO_OFF2);
        int row = tid >> 1, half = tid & 1;
        const float2* wsrc = (const float2*)(Wo + (size_t)row * 64) + half * 16;
#pragma unroll
        for (int j = 0; j < 16; j++) {
            float2 v = wsrc[j];
            wo32[row * 36 + half * 16 + j] = packbf(v.x, v.y);
        }
    }
    float gamma = *gammap;
    __syncthreads();

    // P3: Wo GEMM — warp computes oc [warp*16,+16) x 128 q
    {
        const __nv_bfloat16* wo  = (const __nv_bfloat16*)(smem + WO_OFF2);  // [128][72]
        const __nv_bfloat16* obn = (const __nv_bfloat16*)(smem + OBN_OFF);
        float* st = (float*)smem;                      // [128oc][132q]
        int oc0 = warp * 16;

        uint32_t wA[4][4];
#pragma unroll
        for (int kt = 0; kt < 4; kt++)
            ldsm_x4(wA[kt], smem_u32(&wo[(oc0 + arow) * 72 + kt * 16 + acol]));

        float acc[16][4];
#pragma unroll
        for (int nt = 0; nt < 16; nt++)
#pragma unroll
            for (int i = 0; i < 4; i++) acc[nt][i] = 0.f;
#pragma unroll
        for (int kt = 0; kt < 4; kt++)
#pragma unroll
            for (int nt = 0; nt < 16; nt++) {
                uint32_t bb[2];
                ldsm_x2t(bb, smem_u32(&obn[(kt * 16 + bl) * 136 + nt * 8]));
                mma_bf16(acc[nt], wA[kt], bb);
            }
        __syncthreads();   // obuf/zbuf consumed; st overlay safe
#pragma unroll
        for (int nt = 0; nt < 16; nt++) {
            int oc = oc0 + g, q = nt * 8 + 2 * t;
            *(float2*)&st[oc * 132 + q]       = make_float2(acc[nt][0], acc[nt][1]);
            *(float2*)&st[(oc + 8) * 132 + q] = make_float2(acc[nt][2], acc[nt][3]);
        }
    }
    __syncthreads();

    // P4: out = gamma * st + x
    {
        const float* st = (const float*)smem;
#pragma unroll
        for (int i = 0; i < 16; i++) {
            int e = i * 256 + tid;
            int oc = e >> 5, q4 = (e & 31) * 4;
            float4 v = *(const float4*)&st[oc * 132 + q4];
            size_t idx = ((size_t)b * C_ + oc) * N_ + q0 + q4;
            float4 xv = *(const float4*)&x[idx];
            v.x = fmaf(gamma, v.x, xv.x); v.y = fmaf(gamma, v.y, xv.y);
            v.z = fmaf(gamma, v.z, xv.z); v.w = fmaf(gamma, v.w, xv.w);
            *(float4*)&out[idx] = v;
        }
    }
}

// ---------------------------------------------------------------------------
extern "C" void kernel_launch(void* const* d_in, const int* in_sizes, int n_in,
                              void* d_out, int out_size) {
    const float* x     = (const float*)d_in[0];
    const float* Wth   = (const float*)d_in[1];
    const float* Wph   = (const float*)d_in[2];
    const float* Wg    = (const float*)d_in[3];
    const float* Wo    = (const float*)d_in[4];
    const float* gamma = (const float*)d_in[5];
    float* out = (float*)d_out;

    static int configured = 0;
    if (!configured) {
        cudaFuncSetAttribute(k_proj, cudaFuncAttributeMaxDynamicSharedMemorySize, SMEM_PROJ);
        cudaFuncSetAttribute(k_attn, cudaFuncAttributeMaxDynamicSharedMemorySize, SMEM_ATTN);
        configured = 1;
    }

    k_proj<<<dim3(32, 8), 256, SMEM_PROJ>>>(x, Wth, Wph, Wg);
    k_attn<<<dim3(32, 8), 256, SMEM_ATTN>>>(x, Wo, gamma, out);
}

// round 13
// speedup vs baseline: 1.0710x; 1.0710x over previous
#include <cuda_runtime.h>
#include <cuda_bf16.h>
#include <cuda_fp16.h>
#include <cstdint>

#define B_   8
#define C_   128
#define N_   4096
#define M_   1024
#define DQK  16
#define DV   64

// ---------------- device scratch ----------------
static __device__ __nv_bfloat16 g_theta_bf[B_ * N_ * DQK];   // [b][n][16] (pre-scaled by log2e)
static __device__ __nv_bfloat16 g_phi_bf  [B_ * M_ * DQK];   // [b][m][16]
static __device__ __half        g_gT      [B_ * DV * M_];    // [b][ch][m]  (f16)

// ---------------- helpers ----------------
__device__ __forceinline__ uint32_t smem_u32(const void* p) {
    uint32_t a;
    asm("{ .reg .u64 t; cvta.to.shared.u64 t, %1; cvt.u32.u64 %0, t; }" : "=r"(a) : "l"(p));
    return a;
}
__device__ __forceinline__ void cp16(uint32_t dst, const void* src) {
    asm volatile("cp.async.cg.shared.global [%0], [%1], 16;" :: "r"(dst), "l"(src));
}
#define CP_COMMIT() asm volatile("cp.async.commit_group;" ::: "memory")
#define CP_WAIT(n)  asm volatile("cp.async.wait_group %0;" :: "n"(n) : "memory")

__device__ __forceinline__ void mma_bf16(float d[4], const uint32_t a[4], const uint32_t b[2]) {
    asm volatile("mma.sync.aligned.m16n8k16.row.col.f32.bf16.bf16.f32 "
        "{%0,%1,%2,%3}, {%4,%5,%6,%7}, {%8,%9}, {%0,%1,%2,%3};"
        : "+f"(d[0]), "+f"(d[1]), "+f"(d[2]), "+f"(d[3])
        : "r"(a[0]), "r"(a[1]), "r"(a[2]), "r"(a[3]), "r"(b[0]), "r"(b[1]));
}
__device__ __forceinline__ void mma_f16_f32(float d[4], const uint32_t a[4], const uint32_t b[2]) {
    asm volatile("mma.sync.aligned.m16n8k16.row.col.f32.f16.f16.f32 "
        "{%0,%1,%2,%3}, {%4,%5,%6,%7}, {%8,%9}, {%0,%1,%2,%3};"
        : "+f"(d[0]), "+f"(d[1]), "+f"(d[2]), "+f"(d[3])
        : "r"(a[0]), "r"(a[1]), "r"(a[2]), "r"(a[3]), "r"(b[0]), "r"(b[1]));
}
// f16 accumulator PV MMA (d = 2 regs of f16x2)
__device__ __forceinline__ void mma_f16_f16(uint32_t d[2], const uint32_t a[4], const uint32_t b[2]) {
    asm volatile("mma.sync.aligned.m16n8k16.row.col.f16.f16.f16.f16 "
        "{%0,%1}, {%2,%3,%4,%5}, {%6,%7}, {%0,%1};"
        : "+r"(d[0]), "+r"(d[1])
        : "r"(a[0]), "r"(a[1]), "r"(a[2]), "r"(a[3]), "r"(b[0]), "r"(b[1]));
}
__device__ __forceinline__ uint32_t packbf(float lo, float hi) {
    uint32_t r;
    asm("cvt.rn.satfinite.bf16x2.f32 %0, %1, %2;" : "=r"(r) : "f"(hi), "f"(lo));
    return r;
}
__device__ __forceinline__ uint32_t packh2(float lo, float hi) {
    uint32_t r;
    asm("cvt.rn.f16x2.f32 %0, %1, %2;" : "=r"(r) : "f"(hi), "f"(lo));
    return r;
}
__device__ __forceinline__ uint32_t exh2(uint32_t v) {
    uint32_t r;
    asm("ex2.approx.f16x2 %0, %1;" : "=r"(r) : "r"(v));
    return r;
}
__device__ __forceinline__ void ldsm_x4(uint32_t r[4], uint32_t addr) {
    asm volatile("ldmatrix.sync.aligned.m8n8.x4.shared.b16 {%0,%1,%2,%3}, [%4];"
        : "=r"(r[0]), "=r"(r[1]), "=r"(r[2]), "=r"(r[3]) : "r"(addr));
}
__device__ __forceinline__ void ldsm_x2t(uint32_t r[2], uint32_t addr) {
    asm volatile("ldmatrix.sync.aligned.m8n8.x2.trans.shared.b16 {%0,%1}, [%2];"
        : "=r"(r[0]), "=r"(r[1]) : "r"(addr));
}

// ============================================================================
// Kernel 1: all projections as one bf16 tensor-core GEMM + fused 2x2 pooling.
// theta pre-scaled by log2(e); g stored as f16.  (unchanged)
// ============================================================================
#define PROJ_WS   34816
#define SMEM_PROJ 60928

__global__ void __launch_bounds__(256) k_proj(const float* __restrict__ x,
                       const float* __restrict__ Wth,
                       const float* __restrict__ Wph, const float* __restrict__ Wg) {
    extern __shared__ __align__(16) unsigned char smem[];
    __nv_bfloat16* xs = (__nv_bfloat16*)smem;               // [128][136]
    __nv_bfloat16* ws = (__nv_bfloat16*)(smem + PROJ_WS);   // [96][136]
    int tid = threadIdx.x, b = blockIdx.y, bx = blockIdx.x;
    int n0 = bx * 128;

#pragma unroll
    for (int k = 0; k < 12; k++) {
        int e = k * 256 + tid;
        int row = e >> 5, c4 = e & 31;
        const float* src = (row < 16) ? &Wth[row * 128]
                         : (row < 32) ? &Wph[(row - 16) * 128]
                                      : &Wg[(row - 32) * 128];
        float sc = (row < 16) ? 1.4426950408889634f : 1.0f;
        float4 v = *(const float4*)&src[c4 * 4];
        uint32_t* d = (uint32_t*)&ws[row * 136 + c4 * 4];
        d[0] = packbf(v.x * sc, v.y * sc); d[1] = packbf(v.z * sc, v.w * sc);
    }
    const float* xp = x + ((size_t)b * C_) * N_ + n0;
#pragma unroll
    for (int k = 0; k < 16; k++) {
        int e = k * 256 + tid;
        int ch = e >> 5, p4 = e & 31;
        float4 v = *(const float4*)&xp[(size_t)ch * N_ + p4 * 4];
        uint32_t* d = (uint32_t*)&xs[ch * 136 + p4 * 4];
        d[0] = packbf(v.x, v.y); d[1] = packbf(v.z, v.w);
    }
    __syncthreads();

    int warp = tid >> 5, lane = tid & 31, g = lane >> 2, t = lane & 3;
    int px0 = warp * 16;
    int aq = lane >> 3;
    int ar = (aq & 1) * 8 + (lane & 7), ac = (aq >> 1) * 8;
    int bl = lane & 15;

    float acc[6][2][4];
#pragma unroll
    for (int mi = 0; mi < 6; mi++)
#pragma unroll
        for (int ni = 0; ni < 2; ni++)
#pragma unroll
            for (int i = 0; i < 4; i++) acc[mi][ni][i] = 0.f;

#pragma unroll
    for (int k0 = 0; k0 < 128; k0 += 16) {
        uint32_t bf[2][2];
#pragma unroll
        for (int ni = 0; ni < 2; ni++)
            ldsm_x2t(bf[ni], smem_u32(&xs[(k0 + bl) * 136 + px0 + ni * 8]));
#pragma unroll
        for (int mi = 0; mi < 6; mi++) {
            uint32_t af[4];
            ldsm_x4(af, smem_u32(&ws[(mi * 16 + ar) * 136 + k0 + ac]));
            mma_bf16(acc[mi][0], af, bf[0]);
            mma_bf16(acc[mi][1], af, bf[1]);
        }
    }

#pragma unroll
    for (int ni = 0; ni < 2; ni++) {
        int px = px0 + ni * 8 + 2 * t;
        __nv_bfloat16* base = &g_theta_bf[((size_t)b * N_ + n0 + px) * DQK];
        base[g]          = __float2bfloat16(acc[0][ni][0]);
        base[16 + g]     = __float2bfloat16(acc[0][ni][1]);
        base[g + 8]      = __float2bfloat16(acc[0][ni][2]);
        base[16 + g + 8] = __float2bfloat16(acc[0][ni][3]);
    }

    __syncthreads();
    __nv_bfloat16* st = xs;   // rows 0..15 phi (bf16), rows 16..79 g (f16 bits)
#pragma unroll
    for (int mi = 1; mi < 6; mi++)
#pragma unroll
        for (int ni = 0; ni < 2; ni++) {
            int ro = mi * 16 - 16, pxx = px0 + ni * 8 + 2 * t;
            uint32_t p0, p1;
            if (mi == 1) {
                p0 = packbf(acc[mi][ni][0], acc[mi][ni][1]);
                p1 = packbf(acc[mi][ni][2], acc[mi][ni][3]);
            } else {
                p0 = packh2(acc[mi][ni][0], acc[mi][ni][1]);
                p1 = packh2(acc[mi][ni][2], acc[mi][ni][3]);
            }
            *(uint32_t*)&st[(ro + g) * 136 + pxx]     = p0;
            *(uint32_t*)&st[(ro + g + 8) * 136 + pxx] = p1;
        }
    __syncthreads();

    int cell0 = bx * 32;
#pragma unroll
    for (int k = 0; k < 10; k++) {
        int e = k * 256 + tid;
        int o = e >> 5, q = e & 31;
        if (o < 16) {
            __nv_bfloat162 v0 = *(__nv_bfloat162*)&st[o * 136 + 2 * q];
            __nv_bfloat162 v1 = *(__nv_bfloat162*)&st[o * 136 + 64 + 2 * q];
            float m = fmaxf(fmaxf(__low2float(v0), __high2float(v0)),
                            fmaxf(__low2float(v1), __high2float(v1)));
            g_phi_bf[((size_t)b * M_ + cell0 + q) * DQK + o] = __float2bfloat16(m);
        } else {
            __half2 v0 = *(__half2*)&st[o * 136 + 2 * q];
            __half2 v1 = *(__half2*)&st[o * 136 + 64 + 2 * q];
            float m = fmaxf(fmaxf(__low2float(v0), __high2float(v0)),
                            fmaxf(__low2float(v1), __high2float(v1)));
            g_gT[((size_t)b * DV + (o - 16)) * M_ + cell0 + q] = __float2half(m);
        }
    }
}

// ============================================================================
// Kernel 2: fused attention + W_o + residual.  8 warps x 16 queries (R9 shape)
// with f16 PV accumulators (P scaled by 2^-6; z from SAME scaled P -> o/z
// invariant). Removes 32 regs of accumulator state vs R9 to kill spills.
// smem: [0,6K) theta (48B rows) | [6144,18432) phi x2 (48B rows)
//       [18432,53248) gT x2 ([64ch][272B]) | [53248,70656) Wo bf16 [128][68]
//       epilogue overlay: [0,33792) fp32 staging [64ch][132]
// ============================================================================
#define TH_OFF   0
#define PHI_OFF  6144
#define PHI_BUF  6144
#define BIG_OFF  18432
#define WO_OFF   53248
#define SMEM_ATTN 70656

__global__ void __launch_bounds__(256, 2) k_attn(const float* __restrict__ x,
                      const float* __restrict__ Wo,
                      const float* __restrict__ gammap, float* __restrict__ out) {
    extern __shared__ __align__(16) unsigned char smem[];
    int tid = threadIdx.x, b = blockIdx.y, q0 = blockIdx.x * 128;
    int warp = tid >> 5, lane = tid & 31, g = lane >> 2, t = lane & 3;
    uint32_t sb = smem_u32(smem);
    const uint32_t ONES2 = 0x3C003C00u;
    const float SBIAS = -6.0f;          // P scaled by 2^-6 against f16 overflow

    // ldmatrix lane maps
    int lo   = ((lane >> 4) & 1) * 8 + (lane & 7);
    int hi8  = ((lane >> 3) & 1) * 8;
    int arow = ((lane >> 3) & 1) * 8 + (lane & 7);
    int acol = ((lane >> 4) & 1) * 8;

    // theta: 128 rows x 32B -> 48B-stride rows (256 x cp16)
    cp16(sb + TH_OFF + (tid >> 1) * 48 + (tid & 1) * 16,
         (const char*)&g_theta_bf[((size_t)b * N_ + q0) * DQK] + tid * 16);
    auto issue_chunk = [&](int c, int buf) {
        const char* gsrc = (const char*)&g_gT[((size_t)b * DV) * M_ + c * 128];
        uint32_t gdst = sb + BIG_OFF + buf * 17408;
#pragma unroll
        for (int r = 0; r < 4; r++) {
            int i = r * 256 + tid;
            int ch = i >> 4, off = i & 15;
            cp16(gdst + ch * 272 + off * 16, gsrc + (size_t)ch * 2048 + off * 16);
        }
        cp16(sb + PHI_OFF + buf * PHI_BUF + (tid >> 1) * 48 + (tid & 1) * 16,
             (const char*)&g_phi_bf[((size_t)b * M_ + c * 128) * DQK] + tid * 16);
    };
    issue_chunk(0, 0); CP_COMMIT();

    uint32_t thA[4];
    uint32_t o16[8][2];
    float zacc[4];
#pragma unroll
    for (int n = 0; n < 8; n++) { o16[n][0] = 0u; o16[n][1] = 0u; }
#pragma unroll
    for (int i = 0; i < 4; i++) zacc[i] = 0.f;

    for (int c = 0; c < 8; c++) {
        int buf = c & 1;
        if (c < 7) { issue_chunk(c + 1, buf ^ 1); CP_COMMIT(); CP_WAIT(1); }
        else       { CP_WAIT(0); }
        __syncthreads();

        if (c == 0) {
            const __nv_bfloat16* ths = (const __nv_bfloat16*)(smem + TH_OFF);
            ldsm_x4(thA, smem_u32(&ths[(warp * 16 + arow) * 24 + acol]));
        }
        const __nv_bfloat16* phis = (const __nv_bfloat16*)(smem + PHI_OFF + buf * PHI_BUF);
        const __half* gts = (const __half*)(smem + BIG_OFF + buf * 17408);

#pragma unroll
        for (int kt = 0; kt < 8; kt++) {
            uint32_t pbq[4];
            ldsm_x4(pbq, smem_u32(&phis[(kt * 16 + lo) * 24 + hi8]));
            uint32_t gbq[4][4];
#pragma unroll
            for (int np = 0; np < 4; np++)
                ldsm_x4(gbq[np], smem_u32(&gts[(np * 16 + lo) * 136 + kt * 16 + hi8]));

            float s0[4] = {SBIAS, SBIAS, SBIAS, SBIAS};
            float s1[4] = {SBIAS, SBIAS, SBIAS, SBIAS};
            mma_bf16(s0, thA, &pbq[0]);
            mma_bf16(s1, thA, &pbq[2]);

            // exp: cvt to f16x2 then ex2 -> result IS the packed A-fragment
            uint32_t pa[4];
            pa[0] = exh2(packh2(s0[0], s0[1]));
            pa[1] = exh2(packh2(s0[2], s0[3]));
            pa[2] = exh2(packh2(s1[0], s1[1]));
            pa[3] = exh2(packh2(s1[2], s1[3]));

            uint32_t bones[2] = {ONES2, ONES2};
            mma_f16_f32(zacc, pa, bones);
#pragma unroll
            for (int np = 0; np < 4; np++) {
                mma_f16_f16(o16[2*np],   pa, &gbq[np][0]);
                mma_f16_f16(o16[2*np+1], pa, &gbq[np][2]);
            }
        }
        __syncthreads();
    }

    // ---------------- epilogue: normalize, W_o GEMM, residual ----------------
    // ones-MMA: zacc[0] = z for query row warp*16+g, zacc[2] = row +8
    float inv0 = 1.f / zacc[0], inv1 = 1.f / zacc[2];

    {
        uint32_t* wo32 = (uint32_t*)(smem + WO_OFF);
        int row = tid >> 1, half = tid & 1;
        const float2* wsrc = (const float2*)(Wo + (size_t)row * 64) + half * 16;
#pragma unroll
        for (int j = 0; j < 16; j++) {
            float2 v = wsrc[j];
            wo32[row * 34 + half * 16 + j] = packbf(v.x, v.y);
        }
    }
    // normalized O -> bf16 A-fragments (k = 4 chunks of 16 inch)
    uint32_t pA[4][4];
#pragma unroll
    for (int kt = 0; kt < 4; kt++) {
        float2 a0 = __half22float2(*(__half2*)&o16[2*kt][0]);     // rows g,   ch 2kt*8+2t..+1
        float2 a1 = __half22float2(*(__half2*)&o16[2*kt][1]);     // rows g+8
        float2 b0 = __half22float2(*(__half2*)&o16[2*kt+1][0]);
        float2 b1 = __half22float2(*(__half2*)&o16[2*kt+1][1]);
        pA[kt][0] = packbf(a0.x * inv0, a0.y * inv0);
        pA[kt][1] = packbf(a1.x * inv1, a1.y * inv1);
        pA[kt][2] = packbf(b0.x * inv0, b0.y * inv0);
        pA[kt][3] = packbf(b1.x * inv1, b1.y * inv1);
    }
    float gamma = *gammap;
    __syncthreads();

    const uint32_t* wo32 = (const uint32_t*)(smem + WO_OFF);
    float* st = (float*)smem;

#pragma unroll
    for (int h = 0; h < 2; h++) {
        float acc[8][4];
#pragma unroll
        for (int nb = 0; nb < 8; nb++)
#pragma unroll
            for (int i = 0; i < 4; i++) acc[nb][i] = 0.f;
#pragma unroll
        for (int nb = 0; nb < 8; nb++) {
            int row = (h * 8 + nb) * 8 + g;
#pragma unroll
            for (int kt = 0; kt < 4; kt++) {
                uint32_t gb[2];
                gb[0] = wo32[row * 34 + kt * 8 + t];
                gb[1] = wo32[row * 34 + kt * 8 + t + 4];
                mma_bf16(acc[nb], pA[kt], gb);
            }
        }
        __syncthreads();
#pragma unroll
        for (int nb = 0; nb < 8; nb++) {
            int ch = nb * 8 + 2 * t, q = warp * 16 + g;
            st[ch * 132 + q]           = acc[nb][0];
            st[(ch + 1) * 132 + q]     = acc[nb][1];
            st[ch * 132 + q + 8]       = acc[nb][2];
            st[(ch + 1) * 132 + q + 8] = acc[nb][3];
        }
        __syncthreads();
        const float* xs = x + ((size_t)b * C_ + h * 64) * N_ + q0;
        float* op = out + ((size_t)b * C_ + h * 64) * N_ + q0;
#pragma unroll
        for (int i = 0; i < 8; i++) {
            int e = i * 256 + tid;
            int ch = e >> 5, q4 = (e & 31) * 4;
            float4 v = *(const float4*)&st[ch * 132 + q4];
            float4 xv = *(const float4*)&xs[(size_t)ch * N_ + q4];
            v.x = fmaf(gamma, v.x, xv.x); v.y = fmaf(gamma, v.y, xv.y);
            v.z = fmaf(gamma, v.z, xv.z); v.w = fmaf(gamma, v.w, xv.w);
            *(float4*)&op[(size_t)ch * N_ + q4] = v;
        }
    }
}

// ---------------------------------------------------------------------------
extern "C" void kernel_launch(void* const* d_in, const int* in_sizes, int n_in,
                              void* d_out, int out_size) {
    const float* x     = (const float*)d_in[0];
    const float* Wth   = (const float*)d_in[1];
    const float* Wph   = (const float*)d_in[2];
    const float* Wg    = (const float*)d_in[3];
    const float* Wo    = (const float*)d_in[4];
    const float* gamma = (const float*)d_in[5];
    float* out = (float*)d_out;

    static int configured = 0;
    if (!configured) {
        cudaFuncSetAttribute(k_proj, cudaFuncAttributeMaxDynamicSharedMemorySize, SMEM_PROJ);
        cudaFuncSetAttribute(k_attn, cudaFuncAttributeMaxDynamicSharedMemorySize, SMEM_ATTN);
        configured = 1;
    }

    k_proj<<<dim3(32, 8), 256, SMEM_PROJ>>>(x, Wth, Wph, Wg);
    k_attn<<<dim3(32, 8), 256, SMEM_ATTN>>>(x, Wo, gamma, out);
}